// round 17
// baseline (speedup 1.0000x reference)
#include <cuda_runtime.h>
#include <cuda_bf16.h>

#define NLAY 256
#define TSTEPS 64
#define BATCH 4
#define HDIM 256
#define GDIM 768
#define NCLS 26

// Packed bf16-pair weights, uint4 per (kq, gate-row):
//   uint4 at [(l*32+kq)*768 + row]; u32 component c covers k = kq*8+2c (lo), +1 (hi).
// Matrices: 0=enc_ih 1=enc_hh 2=dec_ih 3=dec_hh, each MATSZ u32s.
#define MATSZ ((size_t)NLAY * 32 * 768 * 4)
__device__ unsigned g_wpack4[4 * MATSZ];

// Sequence slots: enc layer l reads g_seq[l], writes g_seq[l+1] (slot 256 = relu'd emb).
// dec layer d reads g_seq[256] (d==0) else g_seq[d-1], writes g_seq[d].
__device__ float g_seq[NLAY + 1][TSTEPS][BATCH][HDIM];
// One flag per quarter-block: g_flags[4*pairIdx + q], pairIdx 0..511.
__device__ int g_flags[8 * NLAY];

typedef unsigned long long u64;

__device__ __forceinline__ void unpk2(u64 v, float& lo, float& hi) {
    asm("mov.b64 {%0,%1},%2;" : "=f"(lo), "=f"(hi) : "l"(v));
}
__device__ __forceinline__ u64 expand_bf2(unsigned u) {
    float lo = __uint_as_float(u << 16);
    float hi = __uint_as_float(u & 0xffff0000u);
    u64 r; asm("mov.b64 %0,{%1,%2};" : "=l"(r) : "f"(lo), "f"(hi)); return r;
}
__device__ __forceinline__ void fma2(u64& acc, u64 a, u64 b) {
    asm("fma.rn.f32x2 %0,%1,%2,%0;" : "+l"(acc) : "l"(a), "l"(b));
}
__device__ __forceinline__ float sigm(float x) { return 1.f / (1.f + __expf(-x)); }
__device__ __forceinline__ unsigned packbf(float f0, float f1) {
    return (unsigned)__bfloat16_as_ushort(__float2bfloat16(f0)) |
           ((unsigned)__bfloat16_as_ushort(__float2bfloat16(f1)) << 16);
}
__device__ __forceinline__ uint4 ldcg4(const uint4* p) {
    uint4 r;
    asm("ld.global.cg.v4.u32 {%0,%1,%2,%3},[%4];"
        : "=r"(r.x), "=r"(r.y), "=r"(r.z), "=r"(r.w) : "l"(p));
    return r;
}

__global__ void zero_flags_kernel() {
    int i = blockIdx.x * blockDim.x + threadIdx.x;
    if (i < 8 * NLAY) g_flags[i] = 0;
}

// Pointwise convs collapse: seq[0][t][b][h] = X[b,0,2t]*A[h] + C[h]
__global__ void conv_front_kernel(const float* __restrict__ X,
                                  const float* __restrict__ c1w,
                                  const float* __restrict__ c1b,
                                  const float* __restrict__ c2w,
                                  const float* __restrict__ c2b) {
    __shared__ float xs[512];
    int j = threadIdx.x;
    xs[j] = X[j];
    xs[256 + j] = X[256 + j];
    __syncthreads();
    float A = 0.f, C = 0.f;
    for (int c = 0; c < 128; ++c) {
        float w2 = c2w[j * 128 + c];
        A += w2 * c1w[c];
        C += w2 * c1b[c];
    }
    C += c2b[j];
    for (int t = 0; t < TSTEPS; ++t)
        for (int b = 0; b < BATCH; ++b)
            g_seq[0][t][b][j] = xs[b * 128 + 2 * t] * A + C;
}

// Repack fp32 [l][g][k] -> bf16-pair uint4 layout. grid = 4 * 256 * 48 blocks.
__global__ void pack_weights_kernel(const float* __restrict__ eih,
                                    const float* __restrict__ ehh,
                                    const float* __restrict__ dih,
                                    const float* __restrict__ dhh) {
    __shared__ float tile[64][65];
    int bid = blockIdx.x;
    int m = bid / 12288;
    int r = bid % 12288;
    int l = r / 48;
    int r2 = r % 48;
    int gt = r2 / 4;
    int kt = r2 % 4;
    const float* src = (m == 0) ? eih : (m == 1) ? ehh : (m == 2) ? dih : dhh;
    int tid = threadIdx.x;
    #pragma unroll
    for (int i = 0; i < 16; ++i) {
        int idx = tid + i * 256;
        int gg = idx >> 6, kk = idx & 63;
        tile[gg][kk] = src[((size_t)l * GDIM + gt * 64 + gg) * HDIM + kt * 64 + kk];
    }
    __syncthreads();
    #pragma unroll
    for (int i = 0; i < 8; ++i) {
        int o = tid + i * 256;
        int gg = o & 63, kp = o >> 6;
        unsigned u = packbf(tile[gg][2 * kp], tile[gg][2 * kp + 1]);
        size_t dst = (((size_t)l * 32 + kt * 8 + (kp >> 2)) * 768 + gt * 64 + gg) * 4 + (kp & 3);
        g_wpack4[(size_t)m * MATSZ + dst] = u;
    }
}

// Quarter-layer wavefront, K-split fused step.
// 2048 blocks = 512 layers x 4 quarters, 384 threads, 2 blocks/SM.
// Thread = (khalf, rowIdx): khalf = tid/192 covers k in [khalf*128, +128);
// rowIdx = tid%192 -> gate gi=rowIdx/64 (0=r,1=z,2=n), unit u=rowIdx%64,
// global weight row = gi*256 + q*64 + u.
// Per step: ONE fused loop computes partial gx (from x_t) and gh (from h_{t-1});
// partials combined in the gate phase (256 threads = 4 batches x 64 units).
__global__ void __launch_bounds__(384, 2)
gru_wave_kernel(const float* __restrict__ ebih, const float* __restrict__ ebhh,
                const float* __restrict__ dbih, const float* __restrict__ dbhh) {
    __shared__ __align__(16) float xs[1024];        // x_t    [b][k]
    __shared__ __align__(16) float hs[1024];        // h_{t-1}[b][k]
    __shared__ float gxp[2 * 4 * 192];              // [khalf][b][row]
    __shared__ float ghp[2 * 4 * 192];
    __shared__ float bi_s[192], bh_s[192];

    const int bid = blockIdx.x;
    const int tid = threadIdx.x;
    const int pairIdx = bid >> 2;                   // global layer 0..511
    const int q = bid & 3;
    const bool enc = pairIdx < NLAY;
    const int l = pairIdx & (NLAY - 1);
    const int rowIdx = tid % 192;
    const int khalf = tid / 192;                    // 0 or 1
    const int grow = (rowIdx >> 6) * 256 + q * 64 + (rowIdx & 63);

    const uint4* wih0 = (const uint4*)(g_wpack4 + (size_t)(enc ? 0 : 2) * MATSZ)
                        + (((size_t)l * 32 + khalf * 16) * 768 + grow);
    const uint4* whh0 = (const uint4*)(g_wpack4 + (size_t)(enc ? 1 : 3) * MATSZ)
                        + (((size_t)l * 32 + khalf * 16) * 768 + grow);

    const float* inp = enc ? &g_seq[l][0][0][0]
                           : (l == 0 ? &g_seq[NLAY][0][0][0] : &g_seq[l - 1][0][0][0]);
    float* outp = enc ? &g_seq[l + 1][0][0][0] : &g_seq[l][0][0][0];
    const bool relu_out = enc && (l == NLAY - 1);

    // prologue: biases to smem, zero h_{-1}
    if (tid < 192) {
        int gr = (tid >> 6) * 256 + q * 64 + (tid & 63);
        bi_s[tid] = (enc ? ebih : dbih)[l * GDIM + gr];
        bh_s[tid] = (enc ? ebhh : dbhh)[l * GDIM + gr];
    }
    #pragma unroll
    for (int i = 0; i < 3; ++i) {
        int idx = tid + i * 384;
        if (idx < 1024) hs[idx] = 0.f;
    }
    float ho = 0.f;                                 // state in tid<256 (b=tid/64,u=tid%64)

    for (int t = 0; t < TSTEPS; ++t) {
        // --- A: wait prev layer (t) + siblings (t-1); stage x_t, h_{t-1} ---
        if (tid < 8) {
            bool prev = (tid < 4);
            if (!prev || pairIdx > 0) {
                const int* f = prev ? &g_flags[4 * (pairIdx - 1) + tid]
                                    : &g_flags[4 * pairIdx + (tid - 4)];
                int thr = prev ? t : (t - 1);
                int v;
                do {
                    asm volatile("ld.acquire.gpu.global.u32 %0,[%1];"
                                 : "=r"(v) : "l"(f) : "memory");
                    if (v > thr) break;
                    __nanosleep(20);
                } while (true);
            }
        }
        __syncthreads();
        {
            const float* xt = inp + t * 1024;
            const float* ht = outp + (t - 1) * 1024;
            #pragma unroll
            for (int i = 0; i < 3; ++i) {
                int idx = tid + i * 384;
                if (idx < 1024) {
                    xs[idx] = xt[idx];
                    if (t > 0) hs[idx] = ht[idx];
                }
            }
        }
        __syncthreads();

        // --- B: fused ih+hh matvec over own k-half (16 kq) ---
        {
            u64 ax[4] = {0ull, 0ull, 0ull, 0ull};
            u64 ah[4] = {0ull, 0ull, 0ull, 0ull};
            const uint4* wi = wih0;
            const uint4* wh = whh0;
            const float* vx = xs + khalf * 128;
            const float* vh = hs + khalf * 128;
            #pragma unroll 4
            for (int kq = 0; kq < 16; ++kq) {
                uint4 wiw = ldcg4(wi); wi += 768;
                uint4 whw = ldcg4(wh); wh += 768;
                const float* vkx = vx + kq * 8;
                const float* vkh = vh + kq * 8;
                ulonglong2 px0 = *(const ulonglong2*)(vkx);
                ulonglong2 px1 = *(const ulonglong2*)(vkx + 4);
                ulonglong2 px2 = *(const ulonglong2*)(vkx + 256);
                ulonglong2 px3 = *(const ulonglong2*)(vkx + 260);
                ulonglong2 px4 = *(const ulonglong2*)(vkx + 512);
                ulonglong2 px5 = *(const ulonglong2*)(vkx + 516);
                ulonglong2 px6 = *(const ulonglong2*)(vkx + 768);
                ulonglong2 px7 = *(const ulonglong2*)(vkx + 772);
                ulonglong2 ph0 = *(const ulonglong2*)(vkh);
                ulonglong2 ph1 = *(const ulonglong2*)(vkh + 4);
                ulonglong2 ph2 = *(const ulonglong2*)(vkh + 256);
                ulonglong2 ph3 = *(const ulonglong2*)(vkh + 260);
                ulonglong2 ph4 = *(const ulonglong2*)(vkh + 512);
                ulonglong2 ph5 = *(const ulonglong2*)(vkh + 516);
                ulonglong2 ph6 = *(const ulonglong2*)(vkh + 768);
                ulonglong2 ph7 = *(const ulonglong2*)(vkh + 772);
                u64 wv;
                wv = expand_bf2(wiw.x);
                fma2(ax[0], wv, px0.x); fma2(ax[1], wv, px2.x);
                fma2(ax[2], wv, px4.x); fma2(ax[3], wv, px6.x);
                wv = expand_bf2(wiw.y);
                fma2(ax[0], wv, px0.y); fma2(ax[1], wv, px2.y);
                fma2(ax[2], wv, px4.y); fma2(ax[3], wv, px6.y);
                wv = expand_bf2(wiw.z);
                fma2(ax[0], wv, px1.x); fma2(ax[1], wv, px3.x);
                fma2(ax[2], wv, px5.x); fma2(ax[3], wv, px7.x);
                wv = expand_bf2(wiw.w);
                fma2(ax[0], wv, px1.y); fma2(ax[1], wv, px3.y);
                fma2(ax[2], wv, px5.y); fma2(ax[3], wv, px7.y);
                wv = expand_bf2(whw.x);
                fma2(ah[0], wv, ph0.x); fma2(ah[1], wv, ph2.x);
                fma2(ah[2], wv, ph4.x); fma2(ah[3], wv, ph6.x);
                wv = expand_bf2(whw.y);
                fma2(ah[0], wv, ph0.y); fma2(ah[1], wv, ph2.y);
                fma2(ah[2], wv, ph4.y); fma2(ah[3], wv, ph6.y);
                wv = expand_bf2(whw.z);
                fma2(ah[0], wv, ph1.x); fma2(ah[1], wv, ph3.x);
                fma2(ah[2], wv, ph5.x); fma2(ah[3], wv, ph7.x);
                wv = expand_bf2(whw.w);
                fma2(ah[0], wv, ph1.y); fma2(ah[1], wv, ph3.y);
                fma2(ah[2], wv, ph5.y); fma2(ah[3], wv, ph7.y);
            }
            #pragma unroll
            for (int b = 0; b < 4; ++b) {
                float lo, hi;
                unpk2(ax[b], lo, hi);
                gxp[khalf * 768 + b * 192 + rowIdx] = lo + hi;
                unpk2(ah[b], lo, hi);
                ghp[khalf * 768 + b * 192 + rowIdx] = lo + hi;
            }
        }
        __syncthreads();

        // --- C: gates; thread = (b,u) for tid<256 ---
        if (tid < 256) {
            int b = tid >> 6, u = tid & 63;
            float gxr = gxp[b * 192 + u]        + gxp[768 + b * 192 + u]        + bi_s[u];
            float ghr = ghp[b * 192 + u]        + ghp[768 + b * 192 + u]        + bh_s[u];
            float gxz = gxp[b * 192 + 64 + u]   + gxp[768 + b * 192 + 64 + u]   + bi_s[64 + u];
            float ghz = ghp[b * 192 + 64 + u]   + ghp[768 + b * 192 + 64 + u]   + bh_s[64 + u];
            float gxn = gxp[b * 192 + 128 + u]  + gxp[768 + b * 192 + 128 + u]  + bi_s[128 + u];
            float ghn = ghp[b * 192 + 128 + u]  + ghp[768 + b * 192 + 128 + u]  + bh_s[128 + u];
            float r = sigm(gxr + ghr);
            float z = sigm(gxz + ghz);
            float n = tanhf(gxn + r * ghn);
            ho = n + z * (ho - n);                      // (1-z)*n + z*h
            outp[t * 1024 + b * 256 + q * 64 + u] = relu_out ? fmaxf(ho, 0.f) : ho;
        }
        __syncthreads();
        if (tid == 0) {
            asm volatile("st.release.gpu.global.u32 [%0],%1;"
                         :: "l"(&g_flags[4 * pairIdx + q]), "r"(t + 1) : "memory");
        }
    }
}

// Attention + FC + softmax tail. One block per timestep t.
__global__ void attn_fc_kernel(const float* __restrict__ fcl_w,
                               const float* __restrict__ fcl_b,
                               float* __restrict__ out) {
    const int t = blockIdx.x;
    const int tid = threadIdx.x;
    __shared__ float hid_s[BATCH][HDIM];
    __shared__ float sc[BATCH][TSTEPS];
    __shared__ float ctx[BATCH][HDIM];
    __shared__ float lg[BATCH][NCLS];

    #pragma unroll
    for (int b = 0; b < BATCH; ++b)
        hid_s[b][tid] = g_seq[NLAY - 1][t][b][tid];
    __syncthreads();

    int s = tid >> 2, qq = tid & 3;
    #pragma unroll
    for (int b = 0; b < BATCH; ++b) {
        const float* e = &g_seq[NLAY][s][b][0];
        float acc = 0.f;
        for (int d = qq * 64; d < qq * 64 + 64; ++d) acc += hid_s[b][d] * e[d];
        acc += __shfl_xor_sync(0xffffffff, acc, 1);
        acc += __shfl_xor_sync(0xffffffff, acc, 2);
        if (qq == 0) sc[b][s] = acc;
    }
    __syncthreads();

    if (tid < BATCH) {
        int b = tid;
        float m = -1e30f;
        for (int i = 0; i < TSTEPS; ++i) m = fmaxf(m, sc[b][i]);
        float sum = 0.f;
        for (int i = 0; i < TSTEPS; ++i) { float e = __expf(sc[b][i] - m); sc[b][i] = e; sum += e; }
        float inv = 1.f / sum;
        for (int i = 0; i < TSTEPS; ++i) sc[b][i] *= inv;
    }
    __syncthreads();

    #pragma unroll
    for (int b = 0; b < BATCH; ++b) {
        float acc = sc[b][0] * g_seq[NLAY][0][b][tid];
        for (int s2 = 0; s2 < TSTEPS - 1; ++s2)
            acc += sc[b][s2] * g_seq[NLAY][s2 + 1][b][tid];
        ctx[b][tid] = acc;
    }
    __syncthreads();

    if (tid < BATCH * NCLS) {
        int b = tid / NCLS, o = tid % NCLS;
        float acc = fcl_b[o];
        for (int f = 0; f < HDIM; ++f) acc += fcl_w[o * 2 * HDIM + f] * hid_s[b][f];
        for (int f = 0; f < HDIM; ++f) acc += fcl_w[o * 2 * HDIM + HDIM + f] * ctx[b][f];
        lg[b][o] = acc;
    }
    __syncthreads();

    if (tid < BATCH) {
        int b = tid;
        float m = -1e30f;
        for (int o = 0; o < NCLS; ++o) m = fmaxf(m, lg[b][o]);
        float ex[NCLS]; float sum = 0.f;
        for (int o = 0; o < NCLS; ++o) { ex[o] = __expf(lg[b][o] - m); sum += ex[o]; }
        float inv = 1.f / sum;
        for (int o = 0; o < NCLS; ++o)
            out[(t * BATCH + b) * NCLS + o] = ex[o] * inv;
    }
}

extern "C" void kernel_launch(void* const* d_in, const int* in_sizes, int n_in,
                              void* d_out, int out_size) {
    const float* X    = (const float*)d_in[0];
    const float* c1w  = (const float*)d_in[1];
    const float* c1b  = (const float*)d_in[2];
    const float* c2w  = (const float*)d_in[3];
    const float* c2b  = (const float*)d_in[4];
    const float* eih  = (const float*)d_in[5];
    const float* ehh  = (const float*)d_in[6];
    const float* ebih = (const float*)d_in[7];
    const float* ebhh = (const float*)d_in[8];
    const float* dih  = (const float*)d_in[9];
    const float* dhh  = (const float*)d_in[10];
    const float* dbih = (const float*)d_in[11];
    const float* dbhh = (const float*)d_in[12];
    const float* fclw = (const float*)d_in[13];
    const float* fclb = (const float*)d_in[14];
    float* out = (float*)d_out;

    zero_flags_kernel<<<8, 256>>>();
    conv_front_kernel<<<1, 256>>>(X, c1w, c1b, c2w, c2b);
    pack_weights_kernel<<<4 * 256 * 48, 256>>>(eih, ehh, dih, dhh);
    gru_wave_kernel<<<8 * NLAY, 384>>>(ebih, ebhh, dbih, dbhh);
    attn_fc_kernel<<<TSTEPS, 256>>>(fclw, fclb, out);
}